// round 1
// baseline (speedup 1.0000x reference)
#include <cuda_runtime.h>
#include <math.h>

#define NB   16384
#define HID  256
#define TOUT 16

// ---------------- persistent device scratch (no allocs allowed) ----------------
// cells: 0 = enc_speed, 1 = enc_pos, 2 = dec_speed, 3 = dec_cross
__device__ float d_W4h[4][1024 * 256];   // permuted recurrent weights [col'][k]
__device__ float d_W4i[4][1024 * 4];     // permuted input weights    [col'][s]
__device__ float d_b4 [4][1024];         // bih + bhh, permuted
__device__ float d_hbuf[4][2][NB * HID]; // ping-pong hidden state
__device__ float d_cbuf[4][NB * HID];    // cell state (in-place)
__device__ float d_h0c[NB * HID];        // combined decoder init h
__device__ float d_c0c[NB * HID];        // combined decoder init c
__device__ float d_xs[NB * 4];           // speed decoder feedback
__device__ float d_xc[NB * 4];           // crossing decoder feedback

// ---------------- weight permutation ----------------
// col' = tile*128 + gate*32 + ulocal  (tile = col'/128), unit u = tile*32 + ulocal
// original PyTorch row = gate*256 + u  (gate order i,f,g,o)
__global__ void prep_kernel(int cell,
                            const float* __restrict__ Whh,
                            const float* __restrict__ Wih,
                            const float* __restrict__ bih,
                            const float* __restrict__ bhh) {
    int colp = blockIdx.x;           // 0..1023
    int k    = threadIdx.x;          // 0..255
    int g    = (colp & 127) >> 5;
    int u    = ((colp >> 7) << 5) + (colp & 31);
    int orig = g * 256 + u;
    d_W4h[cell][colp * 256 + k] = Whh[orig * 256 + k];
    if (k < 4) d_W4i[cell][colp * 4 + k] = Wih[orig * 4 + k];
    if (k == 0) d_b4[cell][colp] = bih[orig] + bhh[orig];
}

__device__ __forceinline__ float sigf(float x) { return 1.0f / (1.0f + expf(-x)); }

// ---------------- fused LSTM cell step ----------------
// grid: (8 col-tiles, 128 row-tiles, 2 cells), block: 256 threads (16x16)
// Computes g = h@W4h^T (GEMM) + x@W4i^T + b, then gates -> writes h_new, c_new.
template <bool FIRST>
__global__ __launch_bounds__(256, 2) void cell_kernel(
    int cell_base, const float* __restrict__ x0, const float* __restrict__ x1,
    int xstride, int rd, int use_comb, int use_fb)
{
    int cell = cell_base + blockIdx.z;
    const float* x = use_fb ? (blockIdx.z == 0 ? d_xs : d_xc)
                            : (blockIdx.z == 0 ? x0 : x1);
    const float* hin = use_comb ? d_h0c : d_hbuf[cell][rd];
    const float* cin = use_comb ? d_c0c : d_cbuf[cell];
    float* hout = d_hbuf[cell][rd ^ 1];
    float* cout = d_cbuf[cell];
    const float* Wh = d_W4h[cell];

    int row0 = blockIdx.y << 7;
    int col0 = blockIdx.x << 7;
    int tx = threadIdx.x & 15;
    int ty = threadIdx.x >> 4;

    __shared__ float As[128][36];   // h tile, row-major  (reads are broadcast)
    __shared__ float Bs[32][132];   // W tile, k-major    (reads conflict-free)

    float acc[8][8];
    #pragma unroll
    for (int i = 0; i < 8; i++)
        #pragma unroll
        for (int j = 0; j < 8; j++) acc[i][j] = 0.f;

    if (!FIRST) {
        for (int kt = 0; kt < 8; kt++) {
            int k0 = kt << 5;
            #pragma unroll
            for (int i = 0; i < 4; i++) {
                int q  = threadIdx.x + (i << 8);   // 0..1023
                int r  = q >> 3;                   // 0..127
                int kq = (q & 7) << 2;             // 0,4,...,28
                float4 v = *(const float4*)(hin + (size_t)(row0 + r) * HID + k0 + kq);
                *(float4*)&As[r][kq] = v;
                float4 w = *(const float4*)(Wh + (size_t)(col0 + r) * HID + k0 + kq);
                Bs[kq + 0][r] = w.x; Bs[kq + 1][r] = w.y;
                Bs[kq + 2][r] = w.z; Bs[kq + 3][r] = w.w;
            }
            __syncthreads();
            #pragma unroll
            for (int k = 0; k < 32; k++) {
                float a[8], b[8];
                #pragma unroll
                for (int rr = 0; rr < 8; rr++) a[rr] = As[(ty << 3) + rr][k];
                #pragma unroll
                for (int cc = 0; cc < 8; cc++) b[cc] = Bs[k][tx + (cc << 4)];
                #pragma unroll
                for (int rr = 0; rr < 8; rr++)
                    #pragma unroll
                    for (int cc = 0; cc < 8; cc++)
                        acc[rr][cc] = fmaf(a[rr], b[cc], acc[rr][cc]);
            }
            __syncthreads();
        }
    }

    // ---- epilogue: add x@Wi^T + bias, apply LSTM gates, write h,c ----
    float xv[8][4];
    #pragma unroll
    for (int rr = 0; rr < 8; rr++) {
        int row = row0 + (ty << 3) + rr;
        #pragma unroll
        for (int s = 0; s < 4; s++) xv[rr][s] = x[(size_t)row * xstride + s];
    }
    const float* Wi = d_W4i[cell];
    const float* bb = d_b4[cell];
    int ubase = blockIdx.x << 5;   // 32 units per col-tile

    #pragma unroll
    for (int hh = 0; hh < 2; hh++) {
        int u = ubase + tx + (hh << 4);
        float wi[4][4], bg[4];
        #pragma unroll
        for (int g = 0; g < 4; g++) {
            int colp = col0 + (g << 5) + tx + (hh << 4);
            bg[g] = bb[colp];
            #pragma unroll
            for (int s = 0; s < 4; s++) wi[g][s] = Wi[colp * 4 + s];
        }
        #pragma unroll
        for (int rr = 0; rr < 8; rr++) {
            int row = row0 + (ty << 3) + rr;
            float gt[4];
            #pragma unroll
            for (int g = 0; g < 4; g++) {
                float v = acc[rr][(g << 1) + hh] + bg[g];
                #pragma unroll
                for (int s = 0; s < 4; s++) v = fmaf(wi[g][s], xv[rr][s], v);
                gt[g] = v;
            }
            float ig = sigf(gt[0]);
            float fg = sigf(gt[1]);
            float gg = tanhf(gt[2]);
            float og = sigf(gt[3]);
            float cold = FIRST ? 0.f : cin[(size_t)row * HID + u];
            float cn = fmaf(fg, cold, ig * gg);
            float hn = og * tanhf(cn);
            cout[(size_t)row * HID + u] = cn;
            hout[(size_t)row * HID + u] = hn;
        }
    }
}

// ---------------- combine encoder finals: h0 = hsp + hpo, c0 = csp + cpo ----------------
__global__ void combine_kernel() {
    size_t i = (size_t)blockIdx.x * blockDim.x + threadIdx.x;  // float4 index
    const float4* hs = (const float4*)d_hbuf[0][0];
    const float4* hp = (const float4*)d_hbuf[1][0];
    const float4* cs = (const float4*)d_cbuf[0];
    const float4* cp = (const float4*)d_cbuf[1];
    float4 a = hs[i], b = hp[i];
    float4 c = cs[i], d = cp[i];
    float4 ho, co;
    ho.x = a.x + b.x; ho.y = a.y + b.y; ho.z = a.z + b.z; ho.w = a.w + b.w;
    co.x = c.x + d.x; co.y = c.y + d.y; co.z = c.z + d.z; co.w = c.w + d.w;
    ((float4*)d_h0c)[i] = ho;
    ((float4*)d_c0c)[i] = co;
}

// ---------------- decoder heads: one warp per batch row ----------------
__global__ void heads_kernel(int t, int parity,
    const float* __restrict__ fsw, const float* __restrict__ fsb,
    const float* __restrict__ fcw, const float* __restrict__ fcb,
    const float* __restrict__ ew,  const float* __restrict__ eb,
    float* __restrict__ out)
{
    int gtid = blockIdx.x * blockDim.x + threadIdx.x;
    int row  = gtid >> 5;
    int lane = gtid & 31;
    if (row >= NB) return;
    const float* hs = d_hbuf[2][parity] + (size_t)row * HID;
    const float* hc = d_hbuf[3][parity] + (size_t)row * HID;
    float vs[8], vc[8];
    #pragma unroll
    for (int i = 0; i < 8; i++) { vs[i] = hs[lane + 32 * i]; vc[i] = hc[lane + 32 * i]; }

    float r[10];
    #pragma unroll
    for (int o = 0; o < 4; o++) {
        float p = 0.f;
        #pragma unroll
        for (int i = 0; i < 8; i++) p = fmaf(fsw[o * 256 + lane + 32 * i], vs[i], p);
        r[o] = p;
    }
    #pragma unroll
    for (int o = 0; o < 2; o++) {
        float p = 0.f;
        #pragma unroll
        for (int i = 0; i < 8; i++) p = fmaf(fcw[o * 256 + lane + 32 * i], vc[i], p);
        r[4 + o] = p;
    }
    #pragma unroll
    for (int o = 0; o < 4; o++) {
        float p = 0.f;
        #pragma unroll
        for (int i = 0; i < 8; i++) p = fmaf(ew[o * 256 + lane + 32 * i], vc[i], p);
        r[6 + o] = p;
    }
    #pragma unroll
    for (int off = 16; off > 0; off >>= 1)
        #pragma unroll
        for (int o = 0; o < 10; o++) r[o] += __shfl_xor_sync(0xffffffffu, r[o], off);

    if (lane == 0) {
        // speed head: hardtanh(fc_speed(h)), also feedback
        #pragma unroll
        for (int s = 0; s < 4; s++) {
            float v = r[s] + fsb[s];
            v = fminf(fmaxf(v, -100.f), 100.f);
            out[(size_t)row * 64 + t * 4 + s] = v;
            d_xs[row * 4 + s] = v;
        }
        // crossing head: softmax(relu(fc_cross(h)))
        float l0 = fmaxf(r[4] + fcb[0], 0.f);
        float l1 = fmaxf(r[5] + fcb[1], 0.f);
        float m  = fmaxf(l0, l1);
        float e0 = expf(l0 - m), e1 = expf(l1 - m);
        float inv = 1.f / (e0 + e1);
        size_t cb = (size_t)NB * 64;
        out[cb + (size_t)row * 32 + t * 2 + 0] = e0 * inv;
        out[cb + (size_t)row * 32 + t * 2 + 1] = e1 * inv;
        // crossing feedback: relu(emb(h))
        #pragma unroll
        for (int s = 0; s < 4; s++) d_xc[row * 4 + s] = fmaxf(r[6 + s] + eb[s], 0.f);
    }
}

// ---------------- host ----------------
extern "C" void kernel_launch(void* const* d_in, const int* in_sizes, int n_in,
                              void* d_out, int out_size)
{
    (void)in_sizes; (void)n_in; (void)out_size;
    const float* speed = (const float*)d_in[0];
    const float* pos   = (const float*)d_in[1];

    // weight prep (input order: Wih, Whh, bih, bhh per cell, starting at idx 2)
    for (int cell = 0; cell < 4; cell++) {
        int base = 2 + 4 * cell;
        prep_kernel<<<1024, 256>>>(cell,
            (const float*)d_in[base + 1],   // Whh
            (const float*)d_in[base + 0],   // Wih
            (const float*)d_in[base + 2],   // bih
            (const float*)d_in[base + 3]);  // bhh
    }

    dim3 cgrid(8, 128, 2);

    // ---- encoders (cells 0,1), 16 steps ----
    cell_kernel<true><<<cgrid, 256>>>(0, speed, pos, 64, 0, 0, 0);
    for (int t = 1; t < 16; t++)
        cell_kernel<false><<<cgrid, 256>>>(0, speed + 4 * t, pos + 4 * t, 64, t & 1, 0, 0);

    combine_kernel<<<4096, 256>>>();   // NB*HID/4 elems / 256

    // ---- decoders (cells 2,3), 16 steps ----
    const float* fsw = (const float*)d_in[18];
    const float* fsb = (const float*)d_in[19];
    const float* fcw = (const float*)d_in[20];
    const float* fcb = (const float*)d_in[21];
    const float* ew  = (const float*)d_in[22];
    const float* eb  = (const float*)d_in[23];
    float* out = (float*)d_out;

    for (int t = 0; t < TOUT; t++) {
        if (t == 0)
            cell_kernel<false><<<cgrid, 256>>>(2, speed + 60, pos + 60, 64, 0, 1, 0);
        else
            cell_kernel<false><<<cgrid, 256>>>(2, nullptr, nullptr, 4, t & 1, 0, 1);
        heads_kernel<<<2048, 256>>>(t, (t & 1) ^ 1, fsw, fsb, fcw, fcb, ew, eb, out);
    }
}

// round 4
// speedup vs baseline: 3.0833x; 3.0833x over previous
#include <cuda_runtime.h>
#include <math.h>
#include <stdint.h>

#define NB   16384
#define HID  256
#define TOUT 16
#define MSPLIT 9

// ---------------- persistent device scratch ----------------
__device__ float d_W4h[4][1024 * 256];   // permuted recurrent weights [col'][k]
__device__ float d_W4i[4][1024 * 4];
__device__ float d_b4 [4][1024];
__device__ float d_hbuf[4][2][NB * HID];
__device__ float d_cbuf[4][NB * HID];
__device__ float d_h0c[NB * HID];
__device__ float d_c0c[NB * HID];
__device__ float d_xs[NB * 4];
__device__ float d_xc[NB * 4];

__device__ __forceinline__ float sigf(float x) { return 1.0f / (1.0f + expf(-x)); }

__device__ __forceinline__ uint32_t f2tf32(float f) {
    uint32_t o;
    asm("cvt.rna.tf32.f32 %0, %1;" : "=r"(o) : "f"(f));
    return o;
}

__device__ __forceinline__ void mma_tf32(float* d,
    uint32_t a0, uint32_t a1, uint32_t a2, uint32_t a3, uint32_t b0, uint32_t b1) {
    asm volatile("mma.sync.aligned.m16n8k8.row.col.f32.tf32.tf32.f32 "
        "{%0,%1,%2,%3}, {%4,%5,%6,%7}, {%8,%9}, {%0,%1,%2,%3};"
        : "+f"(d[0]), "+f"(d[1]), "+f"(d[2]), "+f"(d[3])
        : "r"(a0), "r"(a1), "r"(a2), "r"(a3), "r"(b0), "r"(b1));
}

// ---------------- SMEM layout (bytes) ----------------
#define SM_WI   0                       // 128 cols * 4 floats          = 2048
#define SM_BI   2048                    // 128 floats                    = 512
#define SM_A    2560                    // 2 * 128 * 36 * 4              = 36864
#define SM_B    39424                   // 8 * 128 * 36 * 4              = 147456
#define SM_TOTAL 186880

// ---------------- weight permutation ----------------
// col' = tile*128 + gate*32 + ulocal ; unit u = tile*32 + ulocal ; orig row = gate*256 + u
__global__ void prep_kernel(int cell,
                            const float* __restrict__ Whh,
                            const float* __restrict__ Wih,
                            const float* __restrict__ bih,
                            const float* __restrict__ bhh) {
    int colp = blockIdx.x;
    int k    = threadIdx.x;
    int g    = (colp & 127) >> 5;
    int u    = ((colp >> 7) << 5) + (colp & 31);
    int orig = g * 256 + u;
    d_W4h[cell][colp * 256 + k] = Whh[orig * 256 + k];
    if (k < 4) d_W4i[cell][colp * 4 + k] = Wih[orig * 4 + k];
    if (k == 0) d_b4[cell][colp] = bih[orig] + bhh[orig];
}

// ---------------- first step (h=c=0) ----------------
__global__ __launch_bounds__(256, 2) void cell_first_kernel(
    const float* __restrict__ x0, const float* __restrict__ x1, int xstride)
{
    int cell = blockIdx.z;
    const float* x = blockIdx.z == 0 ? x0 : x1;
    float* hout = d_hbuf[cell][1];
    float* cout = d_cbuf[cell];
    int row0 = blockIdx.y << 7;
    int col0 = blockIdx.x << 7;
    int tx = threadIdx.x & 15;
    int ty = threadIdx.x >> 4;

    float xv[8][4];
    #pragma unroll
    for (int rr = 0; rr < 8; rr++) {
        int row = row0 + (ty << 3) + rr;
        #pragma unroll
        for (int s = 0; s < 4; s++) xv[rr][s] = x[(size_t)row * xstride + s];
    }
    const float* Wi = d_W4i[cell];
    const float* bb = d_b4[cell];
    int ubase = blockIdx.x << 5;

    #pragma unroll
    for (int hh = 0; hh < 2; hh++) {
        int u = ubase + tx + (hh << 4);
        float wi[4][4], bg[4];
        #pragma unroll
        for (int g = 0; g < 4; g++) {
            int colp = col0 + (g << 5) + tx + (hh << 4);
            bg[g] = bb[colp];
            #pragma unroll
            for (int s = 0; s < 4; s++) wi[g][s] = Wi[colp * 4 + s];
        }
        #pragma unroll
        for (int rr = 0; rr < 8; rr++) {
            int row = row0 + (ty << 3) + rr;
            float gt[4];
            #pragma unroll
            for (int g = 0; g < 4; g++) {
                float v = bg[g];
                #pragma unroll
                for (int s = 0; s < 4; s++) v = fmaf(wi[g][s], xv[rr][s], v);
                gt[g] = v;
            }
            float ig = sigf(gt[0]);
            float gg = tanhf(gt[2]);
            float og = sigf(gt[3]);
            float cn = ig * gg;
            float hn = og * tanhf(cn);
            cout[(size_t)row * HID + u] = cn;
            hout[(size_t)row * HID + u] = hn;
        }
    }
}

// ---------------- tensor-core (mma.sync tf32) LSTM step ----------------
// grid: (8 N-tiles, 2 cells, MSPLIT M-groups), 256 threads = 8 warps.
// CTA keeps weight tile [128 cols][256 k] resident in SMEM (tf32), streams A.
// Warp w computes rows [mtile*128 + w*16, +16) x all 128 cols.
__global__ __launch_bounds__(256, 1) void cell_mma_kernel(
    int cell_base, const float* __restrict__ x0, const float* __restrict__ x1,
    int xstride, int rd, int use_comb, int use_fb)
{
    extern __shared__ char smem[];
    uint32_t* smA = (uint32_t*)(smem + SM_A);   // [2][128][36]
    uint32_t* smB = (uint32_t*)(smem + SM_B);   // [8][128][36]
    float* smWI = (float*)(smem + SM_WI);
    float* smBI = (float*)(smem + SM_BI);

    int tid = threadIdx.x;
    int wid = tid >> 5, lane = tid & 31;
    int gid = lane >> 2, tig = lane & 3;
    int cell = cell_base + blockIdx.y;
    const float* x = use_fb ? (blockIdx.y == 0 ? d_xs : d_xc)
                            : (blockIdx.y == 0 ? x0 : x1);
    const float* hin = use_comb ? d_h0c : d_hbuf[cell][rd];
    const float* cin = use_comb ? d_c0c : d_cbuf[cell];
    float* hout = d_hbuf[cell][rd ^ 1];
    float* cout = d_cbuf[cell];
    const float* Wh = d_W4h[cell];
    int nt = blockIdx.x;
    int col0 = nt << 7;
    int m_lo = (blockIdx.z * 128) / MSPLIT;
    int m_hi = ((blockIdx.z + 1) * 128) / MSPLIT;

    // ---- load resident weight tile (tf32-converted), Wi, bias ----
    {
        int n = tid >> 1, half = tid & 1;
        const float* wrow = Wh + (size_t)(col0 + n) * 256 + half * 16;
        #pragma unroll
        for (int c = 0; c < 8; c++) {
            uint32_t* dst = smB + ((size_t)c * 128 + n) * 36 + half * 16;
            #pragma unroll
            for (int j = 0; j < 4; j++) {
                float4 v = *(const float4*)(wrow + c * 32 + j * 4);
                dst[j * 4 + 0] = f2tf32(v.x);
                dst[j * 4 + 1] = f2tf32(v.y);
                dst[j * 4 + 2] = f2tf32(v.z);
                dst[j * 4 + 3] = f2tf32(v.w);
            }
        }
        if (tid < 128)
            *(float4*)(smWI + tid * 4) = *(const float4*)(d_W4i[cell] + (size_t)(col0 + tid) * 4);
        if (tid < 32)
            *(float4*)(smBI + tid * 4) = *(const float4*)(d_b4[cell] + col0 + tid * 4);
    }
    __syncthreads();

    int r = tid >> 1, half = tid & 1;

    for (int mt = m_lo; mt < m_hi; mt++) {
        int row0 = mt << 7;
        const float* arow = hin + (size_t)(row0 + r) * 256 + half * 16;

        float acc[16][4];
        #pragma unroll
        for (int i = 0; i < 16; i++)
            #pragma unroll
            for (int j = 0; j < 4; j++) acc[i][j] = 0.f;

        float4 va[4];
        #pragma unroll
        for (int j = 0; j < 4; j++) va[j] = *(const float4*)(arow + j * 4);

        for (int c = 0; c < 8; c++) {
            // store prefetched A chunk (tf32) into buffer c&1
            uint32_t* dst = smA + (size_t)((c & 1) * 128 + r) * 36 + half * 16;
            #pragma unroll
            for (int j = 0; j < 4; j++) {
                dst[j * 4 + 0] = f2tf32(va[j].x);
                dst[j * 4 + 1] = f2tf32(va[j].y);
                dst[j * 4 + 2] = f2tf32(va[j].z);
                dst[j * 4 + 3] = f2tf32(va[j].w);
            }
            __syncthreads();
            if (c < 7) {
                #pragma unroll
                for (int j = 0; j < 4; j++)
                    va[j] = *(const float4*)(arow + (c + 1) * 32 + j * 4);
            }
            // compute chunk c
            const uint32_t* Ab = smA + (size_t)((c & 1) * 128 + wid * 16) * 36;
            const uint32_t* Bb = smB + (size_t)c * 128 * 36;
            #pragma unroll
            for (int k8 = 0; k8 < 4; k8++) {
                int kk = k8 * 8;
                uint32_t a0 = Ab[(size_t)gid * 36 + kk + tig];
                uint32_t a1 = Ab[(size_t)(gid + 8) * 36 + kk + tig];
                uint32_t a2 = Ab[(size_t)gid * 36 + kk + tig + 4];
                uint32_t a3 = Ab[(size_t)(gid + 8) * 36 + kk + tig + 4];
                #pragma unroll
                for (int n8 = 0; n8 < 16; n8++) {
                    uint32_t b0 = Bb[(size_t)(n8 * 8 + gid) * 36 + kk + tig];
                    uint32_t b1 = Bb[(size_t)(n8 * 8 + gid) * 36 + kk + tig + 4];
                    mma_tf32(acc[n8], a0, a1, a2, a3, b0, b1);
                }
            }
        }

        // ---- fused LSTM epilogue (all gates local to thread) ----
        #pragma unroll
        for (int rr = 0; rr < 2; rr++) {
            int row = row0 + wid * 16 + gid + rr * 8;
            float xv[4];
            #pragma unroll
            for (int s = 0; s < 4; s++) xv[s] = x[(size_t)row * xstride + s];
            #pragma unroll
            for (int j = 0; j < 4; j++) {
                int ub = 8 * j + 2 * tig;
                float2 cold = *(const float2*)(cin + (size_t)row * HID + nt * 32 + ub);
                float hv[2], cv[2];
                #pragma unroll
                for (int e = 0; e < 2; e++) {
                    int u = ub + e;
                    int ri = rr * 2 + e;
                    float g_i = acc[j     ][ri] + smBI[u];
                    float g_f = acc[j +  4][ri] + smBI[32 + u];
                    float g_g = acc[j +  8][ri] + smBI[64 + u];
                    float g_o = acc[j + 12][ri] + smBI[96 + u];
                    #pragma unroll
                    for (int s = 0; s < 4; s++) {
                        g_i = fmaf(smWI[u * 4 + s],        xv[s], g_i);
                        g_f = fmaf(smWI[(32 + u) * 4 + s], xv[s], g_f);
                        g_g = fmaf(smWI[(64 + u) * 4 + s], xv[s], g_g);
                        g_o = fmaf(smWI[(96 + u) * 4 + s], xv[s], g_o);
                    }
                    float co = (e == 0) ? cold.x : cold.y;
                    float cn = fmaf(sigf(g_f), co, sigf(g_i) * tanhf(g_g));
                    float hn = sigf(g_o) * tanhf(cn);
                    cv[e] = cn; hv[e] = hn;
                }
                *(float2*)(cout + (size_t)row * HID + nt * 32 + ub) = make_float2(cv[0], cv[1]);
                *(float2*)(hout + (size_t)row * HID + nt * 32 + ub) = make_float2(hv[0], hv[1]);
            }
        }
    }
}

// ---------------- combine encoder finals ----------------
__global__ void combine_kernel() {
    size_t i = (size_t)blockIdx.x * blockDim.x + threadIdx.x;
    const float4* hs = (const float4*)d_hbuf[0][0];
    const float4* hp = (const float4*)d_hbuf[1][0];
    const float4* cs = (const float4*)d_cbuf[0];
    const float4* cp = (const float4*)d_cbuf[1];
    float4 a = hs[i], b = hp[i];
    float4 c = cs[i], d = cp[i];
    float4 ho, co;
    ho.x = a.x + b.x; ho.y = a.y + b.y; ho.z = a.z + b.z; ho.w = a.w + b.w;
    co.x = c.x + d.x; co.y = c.y + d.y; co.z = c.z + d.z; co.w = c.w + d.w;
    ((float4*)d_h0c)[i] = ho;
    ((float4*)d_c0c)[i] = co;
}

// ---------------- decoder heads ----------------
__global__ void heads_kernel(int t, int parity,
    const float* __restrict__ fsw, const float* __restrict__ fsb,
    const float* __restrict__ fcw, const float* __restrict__ fcb,
    const float* __restrict__ ew,  const float* __restrict__ eb,
    float* __restrict__ out)
{
    int gtid = blockIdx.x * blockDim.x + threadIdx.x;
    int row  = gtid >> 5;
    int lane = gtid & 31;
    if (row >= NB) return;
    const float* hs = d_hbuf[2][parity] + (size_t)row * HID;
    const float* hc = d_hbuf[3][parity] + (size_t)row * HID;
    float vs[8], vc[8];
    #pragma unroll
    for (int i = 0; i < 8; i++) { vs[i] = hs[lane + 32 * i]; vc[i] = hc[lane + 32 * i]; }

    float r[10];
    #pragma unroll
    for (int o = 0; o < 4; o++) {
        float p = 0.f;
        #pragma unroll
        for (int i = 0; i < 8; i++) p = fmaf(fsw[o * 256 + lane + 32 * i], vs[i], p);
        r[o] = p;
    }
    #pragma unroll
    for (int o = 0; o < 2; o++) {
        float p = 0.f;
        #pragma unroll
        for (int i = 0; i < 8; i++) p = fmaf(fcw[o * 256 + lane + 32 * i], vc[i], p);
        r[4 + o] = p;
    }
    #pragma unroll
    for (int o = 0; o < 4; o++) {
        float p = 0.f;
        #pragma unroll
        for (int i = 0; i < 8; i++) p = fmaf(ew[o * 256 + lane + 32 * i], vc[i], p);
        r[6 + o] = p;
    }
    #pragma unroll
    for (int off = 16; off > 0; off >>= 1)
        #pragma unroll
        for (int o = 0; o < 10; o++) r[o] += __shfl_xor_sync(0xffffffffu, r[o], off);

    if (lane == 0) {
        #pragma unroll
        for (int s = 0; s < 4; s++) {
            float v = r[s] + fsb[s];
            v = fminf(fmaxf(v, -100.f), 100.f);
            out[(size_t)row * 64 + t * 4 + s] = v;
            d_xs[row * 4 + s] = v;
        }
        float l0 = fmaxf(r[4] + fcb[0], 0.f);
        float l1 = fmaxf(r[5] + fcb[1], 0.f);
        float m  = fmaxf(l0, l1);
        float e0 = expf(l0 - m), e1 = expf(l1 - m);
        float inv = 1.f / (e0 + e1);
        size_t cb = (size_t)NB * 64;
        out[cb + (size_t)row * 32 + t * 2 + 0] = e0 * inv;
        out[cb + (size_t)row * 32 + t * 2 + 1] = e1 * inv;
        #pragma unroll
        for (int s = 0; s < 4; s++) d_xc[row * 4 + s] = fmaxf(r[6 + s] + eb[s], 0.f);
    }
}

// ---------------- host ----------------
extern "C" void kernel_launch(void* const* d_in, const int* in_sizes, int n_in,
                              void* d_out, int out_size)
{
    (void)in_sizes; (void)n_in; (void)out_size;
    const float* speed = (const float*)d_in[0];
    const float* pos   = (const float*)d_in[1];

    cudaFuncSetAttribute(cell_mma_kernel, cudaFuncAttributeMaxDynamicSharedMemorySize, SM_TOTAL);

    for (int cell = 0; cell < 4; cell++) {
        int base = 2 + 4 * cell;
        prep_kernel<<<1024, 256>>>(cell,
            (const float*)d_in[base + 1],
            (const float*)d_in[base + 0],
            (const float*)d_in[base + 2],
            (const float*)d_in[base + 3]);
    }

    dim3 tgrid(8, 2, MSPLIT);

    // ---- encoders ----
    cell_first_kernel<<<dim3(8, 128, 2), 256>>>(speed, pos, 64);
    for (int t = 1; t < 16; t++)
        cell_mma_kernel<<<tgrid, 256, SM_TOTAL>>>(0, speed + 4 * t, pos + 4 * t, 64, t & 1, 0, 0);

    combine_kernel<<<4096, 256>>>();

    // ---- decoders ----
    const float* fsw = (const float*)d_in[18];
    const float* fsb = (const float*)d_in[19];
    const float* fcw = (const float*)d_in[20];
    const float* fcb = (const float*)d_in[21];
    const float* ew  = (const float*)d_in[22];
    const float* eb  = (const float*)d_in[23];
    float* out = (float*)d_out;

    for (int t = 0; t < TOUT; t++) {
        if (t == 0)
            cell_mma_kernel<<<tgrid, 256, SM_TOTAL>>>(2, speed + 60, pos + 60, 64, 0, 1, 0);
        else
            cell_mma_kernel<<<tgrid, 256, SM_TOTAL>>>(2, nullptr, nullptr, 4, t & 1, 0, 1);
        heads_kernel<<<2048, 256>>>(t, (t & 1) ^ 1, fsw, fsb, fcw, fcb, ew, eb, out);
    }
}

// round 5
// speedup vs baseline: 4.4868x; 1.4552x over previous
#include <cuda_runtime.h>
#include <cuda_fp16.h>
#include <math.h>
#include <stdint.h>

#define NB   16384
#define HID  256
#define TOUT 16
#define MSPLIT 9

// ---------------- persistent device scratch ----------------
__device__ float  d_W4h[4][1024 * 256];   // permuted recurrent weights [col'][k] (fp32)
__device__ float  d_W4i[4][1024 * 4];
__device__ float  d_b4 [4][1024];
__device__ __half d_hbuf[4][2][NB * HID]; // hidden state, fp16
__device__ float  d_cbuf[4][NB * HID];    // cell state, fp32
__device__ __half d_h0c[NB * HID];
__device__ float  d_c0c[NB * HID];
__device__ float  d_xs[NB * 4];
__device__ float  d_xc[NB * 4];

__device__ __forceinline__ float sigf(float x) { return 1.0f / (1.0f + expf(-x)); }

__device__ __forceinline__ void mma_f16(float* d,
    uint32_t a0, uint32_t a1, uint32_t a2, uint32_t a3, uint32_t b0, uint32_t b1) {
    asm volatile("mma.sync.aligned.m16n8k16.row.col.f32.f16.f16.f32 "
        "{%0,%1,%2,%3}, {%4,%5,%6,%7}, {%8,%9}, {%0,%1,%2,%3};"
        : "+f"(d[0]), "+f"(d[1]), "+f"(d[2]), "+f"(d[3])
        : "r"(a0), "r"(a1), "r"(a2), "r"(a3), "r"(b0), "r"(b1));
}

// ---------------- SMEM layout ----------------
// word = uint32 holding half2 (2 halfs along k). Row stride 20 words (16 data + 4 pad)
#define AW 20
#define SM_WI   0                        // 128*4 floats = 2048 B
#define SM_BI   2048                     // 512 B
#define SM_A    2560                     // 2*128*20*4 = 20480 B
#define SM_B    23040                    // 8*128*20*4 = 81920 B
#define SM_TOTAL 104960

// ---------------- weight permutation ----------------
__global__ void prep_kernel(int cell,
                            const float* __restrict__ Whh,
                            const float* __restrict__ Wih,
                            const float* __restrict__ bih,
                            const float* __restrict__ bhh) {
    int colp = blockIdx.x;
    int k    = threadIdx.x;
    int g    = (colp & 127) >> 5;
    int u    = ((colp >> 7) << 5) + (colp & 31);
    int orig = g * 256 + u;
    d_W4h[cell][colp * 256 + k] = Whh[orig * 256 + k];
    if (k < 4) d_W4i[cell][colp * 4 + k] = Wih[orig * 4 + k];
    if (k == 0) d_b4[cell][colp] = bih[orig] + bhh[orig];
}

// ---------------- first step (h=c=0) ----------------
__global__ __launch_bounds__(256, 2) void cell_first_kernel(
    const float* __restrict__ x0, const float* __restrict__ x1, int xstride)
{
    int cell = blockIdx.z;
    const float* x = blockIdx.z == 0 ? x0 : x1;
    __half* hout = d_hbuf[cell][1];
    float*  cout = d_cbuf[cell];
    int row0 = blockIdx.y << 7;
    int col0 = blockIdx.x << 7;
    int tx = threadIdx.x & 15;
    int ty = threadIdx.x >> 4;

    float xv[8][4];
    #pragma unroll
    for (int rr = 0; rr < 8; rr++) {
        int row = row0 + (ty << 3) + rr;
        #pragma unroll
        for (int s = 0; s < 4; s++) xv[rr][s] = x[(size_t)row * xstride + s];
    }
    const float* Wi = d_W4i[cell];
    const float* bb = d_b4[cell];
    int ubase = blockIdx.x << 5;

    #pragma unroll
    for (int hh = 0; hh < 2; hh++) {
        int u = ubase + tx + (hh << 4);
        float wi[4][4], bg[4];
        #pragma unroll
        for (int g = 0; g < 4; g++) {
            int colp = col0 + (g << 5) + tx + (hh << 4);
            bg[g] = bb[colp];
            #pragma unroll
            for (int s = 0; s < 4; s++) wi[g][s] = Wi[colp * 4 + s];
        }
        #pragma unroll
        for (int rr = 0; rr < 8; rr++) {
            int row = row0 + (ty << 3) + rr;
            float gt[4];
            #pragma unroll
            for (int g = 0; g < 4; g++) {
                float v = bg[g];
                #pragma unroll
                for (int s = 0; s < 4; s++) v = fmaf(wi[g][s], xv[rr][s], v);
                gt[g] = v;
            }
            float ig = sigf(gt[0]);
            float gg = tanhf(gt[2]);
            float og = sigf(gt[3]);
            float cn = ig * gg;
            float hn = og * tanhf(cn);
            cout[(size_t)row * HID + u] = cn;
            hout[(size_t)row * HID + u] = __float2half(hn);
        }
    }
}

// ---------------- fp16 mma.sync LSTM step ----------------
// grid (8 N-tiles, 2 cells, MSPLIT M-groups), 256 threads = 8 warps.
// B (weights, fp16) resident in SMEM; A (h, fp16) streamed per 32-k chunk.
__global__ __launch_bounds__(256, 1) void cell_mma_kernel(
    int cell_base, const float* __restrict__ x0, const float* __restrict__ x1,
    int xstride, int rd, int use_comb, int use_fb)
{
    extern __shared__ char smem[];
    uint32_t* smA = (uint32_t*)(smem + SM_A);   // [2][128][AW]
    uint32_t* smB = (uint32_t*)(smem + SM_B);   // [8][128][AW]
    float* smWI = (float*)(smem + SM_WI);
    float* smBI = (float*)(smem + SM_BI);

    int tid = threadIdx.x;
    int wid = tid >> 5, lane = tid & 31;
    int gid = lane >> 2, tig = lane & 3;
    int cell = cell_base + blockIdx.y;
    const float* x = use_fb ? (blockIdx.y == 0 ? d_xs : d_xc)
                            : (blockIdx.y == 0 ? x0 : x1);
    const __half* hin = use_comb ? d_h0c : d_hbuf[cell][rd];
    const float*  cin = use_comb ? d_c0c : d_cbuf[cell];
    __half* hout = d_hbuf[cell][rd ^ 1];
    float*  cout = d_cbuf[cell];
    const float* Wh = d_W4h[cell];
    int nt = blockIdx.x;
    int col0 = nt << 7;
    int m_lo = (blockIdx.z * 128) / MSPLIT;
    int m_hi = ((blockIdx.z + 1) * 128) / MSPLIT;

    int r = tid >> 1, half = tid & 1;

    // ---- load resident weight tile (fp32 -> half2), Wi, bias ----
    {
        const float* wrow = Wh + (size_t)(col0 + r) * 256 + half * 16;
        #pragma unroll
        for (int c = 0; c < 8; c++) {
            const float* src = wrow + c * 32;
            uint32_t w[8];
            #pragma unroll
            for (int j = 0; j < 8; j++) {
                __half2 h2 = __floats2half2_rn(src[2 * j], src[2 * j + 1]);
                w[j] = *(uint32_t*)&h2;
            }
            uint32_t* dst = smB + ((size_t)c * 128 + r) * AW + half * 8;
            *(uint4*)(dst)     = make_uint4(w[0], w[1], w[2], w[3]);
            *(uint4*)(dst + 4) = make_uint4(w[4], w[5], w[6], w[7]);
        }
        if (tid < 128)
            *(float4*)(smWI + tid * 4) = *(const float4*)(d_W4i[cell] + (size_t)(col0 + tid) * 4);
        if (tid < 32)
            *(float4*)(smBI + tid * 4) = *(const float4*)(d_b4[cell] + col0 + tid * 4);
    }
    __syncthreads();

    for (int mt = m_lo; mt < m_hi; mt++) {
        int row0 = mt << 7;
        // thread (r, half) covers 16 halfs (= 8 words) of each 32-half chunk
        const uint4* arow = (const uint4*)(hin + (size_t)(row0 + r) * 256 + half * 16);
        // chunk c starts at half offset c*32 -> uint4 index c*4 (+1 for upper 8 halfs)

        float acc[16][4];
        #pragma unroll
        for (int i = 0; i < 16; i++)
            #pragma unroll
            for (int j = 0; j < 4; j++) acc[i][j] = 0.f;

        uint4 va0 = arow[0], va1 = arow[1];

        for (int c = 0; c < 8; c++) {
            uint32_t* dst = smA + (size_t)((c & 1) * 128 + r) * AW + half * 8;
            *(uint4*)(dst)     = va0;
            *(uint4*)(dst + 4) = va1;
            __syncthreads();
            if (c < 7) {
                va0 = arow[(c + 1) * 4 + 0];
                va1 = arow[(c + 1) * 4 + 1];
            }
            const uint32_t* Ab = smA + (size_t)((c & 1) * 128 + wid * 16) * AW;
            const uint32_t* Bb = smB + (size_t)c * 128 * AW;
            #pragma unroll
            for (int s = 0; s < 2; s++) {
                int kk = s * 8;
                uint32_t a0 = Ab[(size_t)gid * AW + kk + tig];
                uint32_t a1 = Ab[(size_t)(gid + 8) * AW + kk + tig];
                uint32_t a2 = Ab[(size_t)gid * AW + kk + tig + 4];
                uint32_t a3 = Ab[(size_t)(gid + 8) * AW + kk + tig + 4];
                #pragma unroll
                for (int n8 = 0; n8 < 16; n8++) {
                    uint32_t b0 = Bb[(size_t)(n8 * 8 + gid) * AW + kk + tig];
                    uint32_t b1 = Bb[(size_t)(n8 * 8 + gid) * AW + kk + tig + 4];
                    mma_f16(acc[n8], a0, a1, a2, a3, b0, b1);
                }
            }
            if (c < 7) __syncthreads();
        }

        // ---- fused LSTM epilogue ----
        #pragma unroll
        for (int rr = 0; rr < 2; rr++) {
            int row = row0 + wid * 16 + gid + rr * 8;
            float xv[4];
            #pragma unroll
            for (int s = 0; s < 4; s++) xv[s] = x[(size_t)row * xstride + s];
            #pragma unroll
            for (int j = 0; j < 4; j++) {
                int ub = 8 * j + 2 * tig;
                float2 cold = *(const float2*)(cin + (size_t)row * HID + nt * 32 + ub);
                float hv[2], cv[2];
                #pragma unroll
                for (int e = 0; e < 2; e++) {
                    int u = ub + e;
                    int ri = rr * 2 + e;
                    float g_i = acc[j     ][ri] + smBI[u];
                    float g_f = acc[j +  4][ri] + smBI[32 + u];
                    float g_g = acc[j +  8][ri] + smBI[64 + u];
                    float g_o = acc[j + 12][ri] + smBI[96 + u];
                    #pragma unroll
                    for (int s = 0; s < 4; s++) {
                        g_i = fmaf(smWI[u * 4 + s],        xv[s], g_i);
                        g_f = fmaf(smWI[(32 + u) * 4 + s], xv[s], g_f);
                        g_g = fmaf(smWI[(64 + u) * 4 + s], xv[s], g_g);
                        g_o = fmaf(smWI[(96 + u) * 4 + s], xv[s], g_o);
                    }
                    float co = (e == 0) ? cold.x : cold.y;
                    float cn = fmaf(sigf(g_f), co, sigf(g_i) * tanhf(g_g));
                    float hn = sigf(g_o) * tanhf(cn);
                    cv[e] = cn; hv[e] = hn;
                }
                *(float2*)(cout + (size_t)row * HID + nt * 32 + ub) = make_float2(cv[0], cv[1]);
                *(__half2*)(hout + (size_t)row * HID + nt * 32 + ub) = __floats2half2_rn(hv[0], hv[1]);
            }
        }
        if (mt + 1 < m_hi) __syncthreads();
    }
}

// ---------------- combine encoder finals ----------------
__global__ void combine_kernel() {
    size_t i = (size_t)blockIdx.x * blockDim.x + threadIdx.x;  // 0 .. NB*HID/4-1
    // c: fp32, float4
    float4 c0 = ((const float4*)d_cbuf[0])[i];
    float4 c1 = ((const float4*)d_cbuf[1])[i];
    ((float4*)d_c0c)[i] = make_float4(c0.x + c1.x, c0.y + c1.y, c0.z + c1.z, c0.w + c1.w);
    // h: fp16, 4 halfs = 2 half2
    const __half2* ha = (const __half2*)d_hbuf[0][0];
    const __half2* hb = (const __half2*)d_hbuf[1][0];
    __half2* ho = (__half2*)d_h0c;
    #pragma unroll
    for (int j = 0; j < 2; j++) {
        float2 a = __half22float2(ha[2 * i + j]);
        float2 b = __half22float2(hb[2 * i + j]);
        ho[2 * i + j] = __floats2half2_rn(a.x + b.x, a.y + b.y);
    }
}

// ---------------- decoder heads ----------------
__global__ void heads_kernel(int t, int parity,
    const float* __restrict__ fsw, const float* __restrict__ fsb,
    const float* __restrict__ fcw, const float* __restrict__ fcb,
    const float* __restrict__ ew,  const float* __restrict__ eb,
    float* __restrict__ out)
{
    int gtid = blockIdx.x * blockDim.x + threadIdx.x;
    int row  = gtid >> 5;
    int lane = gtid & 31;
    if (row >= NB) return;
    const __half* hs = d_hbuf[2][parity] + (size_t)row * HID;
    const __half* hc = d_hbuf[3][parity] + (size_t)row * HID;
    float vs[8], vc[8];
    #pragma unroll
    for (int i = 0; i < 8; i++) {
        vs[i] = __half2float(hs[lane + 32 * i]);
        vc[i] = __half2float(hc[lane + 32 * i]);
    }

    float r[10];
    #pragma unroll
    for (int o = 0; o < 4; o++) {
        float p = 0.f;
        #pragma unroll
        for (int i = 0; i < 8; i++) p = fmaf(fsw[o * 256 + lane + 32 * i], vs[i], p);
        r[o] = p;
    }
    #pragma unroll
    for (int o = 0; o < 2; o++) {
        float p = 0.f;
        #pragma unroll
        for (int i = 0; i < 8; i++) p = fmaf(fcw[o * 256 + lane + 32 * i], vc[i], p);
        r[4 + o] = p;
    }
    #pragma unroll
    for (int o = 0; o < 4; o++) {
        float p = 0.f;
        #pragma unroll
        for (int i = 0; i < 8; i++) p = fmaf(ew[o * 256 + lane + 32 * i], vc[i], p);
        r[6 + o] = p;
    }
    #pragma unroll
    for (int off = 16; off > 0; off >>= 1)
        #pragma unroll
        for (int o = 0; o < 10; o++) r[o] += __shfl_xor_sync(0xffffffffu, r[o], off);

    if (lane == 0) {
        #pragma unroll
        for (int s = 0; s < 4; s++) {
            float v = r[s] + fsb[s];
            v = fminf(fmaxf(v, -100.f), 100.f);
            out[(size_t)row * 64 + t * 4 + s] = v;
            d_xs[row * 4 + s] = v;
        }
        float l0 = fmaxf(r[4] + fcb[0], 0.f);
        float l1 = fmaxf(r[5] + fcb[1], 0.f);
        float m  = fmaxf(l0, l1);
        float e0 = expf(l0 - m), e1 = expf(l1 - m);
        float inv = 1.f / (e0 + e1);
        size_t cb = (size_t)NB * 64;
        out[cb + (size_t)row * 32 + t * 2 + 0] = e0 * inv;
        out[cb + (size_t)row * 32 + t * 2 + 1] = e1 * inv;
        #pragma unroll
        for (int s = 0; s < 4; s++) d_xc[row * 4 + s] = fmaxf(r[6 + s] + eb[s], 0.f);
    }
}

// ---------------- host ----------------
extern "C" void kernel_launch(void* const* d_in, const int* in_sizes, int n_in,
                              void* d_out, int out_size)
{
    (void)in_sizes; (void)n_in; (void)out_size;
    const float* speed = (const float*)d_in[0];
    const float* pos   = (const float*)d_in[1];

    cudaFuncSetAttribute(cell_mma_kernel, cudaFuncAttributeMaxDynamicSharedMemorySize, SM_TOTAL);

    for (int cell = 0; cell < 4; cell++) {
        int base = 2 + 4 * cell;
        prep_kernel<<<1024, 256>>>(cell,
            (const float*)d_in[base + 1],
            (const float*)d_in[base + 0],
            (const float*)d_in[base + 2],
            (const float*)d_in[base + 3]);
    }

    dim3 tgrid(8, 2, MSPLIT);

    // ---- encoders ----
    cell_first_kernel<<<dim3(8, 128, 2), 256>>>(speed, pos, 64);
    for (int t = 1; t < 16; t++)
        cell_mma_kernel<<<tgrid, 256, SM_TOTAL>>>(0, speed + 4 * t, pos + 4 * t, 64, t & 1, 0, 0);

    combine_kernel<<<4096, 256>>>();

    // ---- decoders ----
    const float* fsw = (const float*)d_in[18];
    const float* fsb = (const float*)d_in[19];
    const float* fcw = (const float*)d_in[20];
    const float* fcb = (const float*)d_in[21];
    const float* ew  = (const float*)d_in[22];
    const float* eb  = (const float*)d_in[23];
    float* out = (float*)d_out;

    for (int t = 0; t < TOUT; t++) {
        if (t == 0)
            cell_mma_kernel<<<tgrid, 256, SM_TOTAL>>>(2, speed + 60, pos + 60, 64, 0, 1, 0);
        else
            cell_mma_kernel<<<tgrid, 256, SM_TOTAL>>>(2, nullptr, nullptr, 4, t & 1, 0, 1);
        heads_kernel<<<2048, 256>>>(t, (t & 1) ^ 1, fsw, fsb, fcw, fcb, ew, eb, out);
    }
}

// round 6
// speedup vs baseline: 5.8022x; 1.2932x over previous
#include <cuda_runtime.h>
#include <cuda_fp16.h>
#include <math.h>
#include <stdint.h>

#define NB   16384
#define HID  256
#define TOUT 16
#define MSPLIT 9

// ---------------- persistent device scratch ----------------
__device__ float  d_W4h[4][1024 * 256];   // permuted recurrent weights [col'][k] (fp32)
__device__ float  d_W4i[4][1024 * 4];
__device__ float  d_b4 [4][1024];
__device__ __half d_hbuf[4][2][NB * HID]; // hidden state, fp16
__device__ float  d_cbuf[4][NB * HID];    // cell state, fp32
__device__ __half d_h0c[NB * HID];
__device__ float  d_c0c[NB * HID];
__device__ float  d_xs[NB * 4];
__device__ float  d_xc[NB * 4];

__device__ __forceinline__ float sigf(float x) { return 1.0f / (1.0f + expf(-x)); }

// fast activations (MUFU-based); callers clamp input to [-30, 30]
__device__ __forceinline__ float sig_fast(float x) {
    float e = __expf(-x);
    return __fdividef(1.0f, 1.0f + e);
}
__device__ __forceinline__ float tanh_fast(float x) {
    float e = __expf(-2.0f * x);
    return (1.0f - e) * __fdividef(1.0f, 1.0f + e);
}
__device__ __forceinline__ float gclamp(float x) {
    return fminf(fmaxf(x, -30.0f), 30.0f);
}

// fp16 mma with fp16 accumulators (d = 2x b32 regs, each half2)
__device__ __forceinline__ void mma_f16acc(uint32_t* d,
    uint32_t a0, uint32_t a1, uint32_t a2, uint32_t a3, uint32_t b0, uint32_t b1) {
    asm volatile("mma.sync.aligned.m16n8k16.row.col.f16.f16.f16.f16 "
        "{%0,%1}, {%2,%3,%4,%5}, {%6,%7}, {%0,%1};"
        : "+r"(d[0]), "+r"(d[1])
        : "r"(a0), "r"(a1), "r"(a2), "r"(a3), "r"(b0), "r"(b1));
}

// ---------------- SMEM layout ----------------
// word = uint32 holding half2 (2 halfs along k). Row stride 20 words (16 data + 4 pad)
#define AW 20
#define SM_WI   0                        // 128*4 floats = 2048 B
#define SM_BI   2048                     // 512 B
#define SM_A    2560                     // 2*128*20*4 = 20480 B
#define SM_B    23040                    // 8*128*20*4 = 81920 B
#define SM_TOTAL 104960

// ---------------- weight permutation ----------------
__global__ void prep_kernel(int cell,
                            const float* __restrict__ Whh,
                            const float* __restrict__ Wih,
                            const float* __restrict__ bih,
                            const float* __restrict__ bhh) {
    int colp = blockIdx.x;
    int k    = threadIdx.x;
    int g    = (colp & 127) >> 5;
    int u    = ((colp >> 7) << 5) + (colp & 31);
    int orig = g * 256 + u;
    d_W4h[cell][colp * 256 + k] = Whh[orig * 256 + k];
    if (k < 4) d_W4i[cell][colp * 4 + k] = Wih[orig * 4 + k];
    if (k == 0) d_b4[cell][colp] = bih[orig] + bhh[orig];
}

// ---------------- first step (h=c=0) ----------------
__global__ __launch_bounds__(256, 2) void cell_first_kernel(
    const float* __restrict__ x0, const float* __restrict__ x1, int xstride)
{
    int cell = blockIdx.z;
    const float* x = blockIdx.z == 0 ? x0 : x1;
    __half* hout = d_hbuf[cell][1];
    float*  cout = d_cbuf[cell];
    int row0 = blockIdx.y << 7;
    int col0 = blockIdx.x << 7;
    int tx = threadIdx.x & 15;
    int ty = threadIdx.x >> 4;

    float xv[8][4];
    #pragma unroll
    for (int rr = 0; rr < 8; rr++) {
        int row = row0 + (ty << 3) + rr;
        #pragma unroll
        for (int s = 0; s < 4; s++) xv[rr][s] = x[(size_t)row * xstride + s];
    }
    const float* Wi = d_W4i[cell];
    const float* bb = d_b4[cell];
    int ubase = blockIdx.x << 5;

    #pragma unroll
    for (int hh = 0; hh < 2; hh++) {
        int u = ubase + tx + (hh << 4);
        float wi[4][4], bg[4];
        #pragma unroll
        for (int g = 0; g < 4; g++) {
            int colp = col0 + (g << 5) + tx + (hh << 4);
            bg[g] = bb[colp];
            #pragma unroll
            for (int s = 0; s < 4; s++) wi[g][s] = Wi[colp * 4 + s];
        }
        #pragma unroll
        for (int rr = 0; rr < 8; rr++) {
            int row = row0 + (ty << 3) + rr;
            float gt[4];
            #pragma unroll
            for (int g = 0; g < 4; g++) {
                float v = bg[g];
                #pragma unroll
                for (int s = 0; s < 4; s++) v = fmaf(wi[g][s], xv[rr][s], v);
                gt[g] = v;
            }
            float ig = sigf(gt[0]);
            float gg = tanhf(gt[2]);
            float og = sigf(gt[3]);
            float cn = ig * gg;
            float hn = og * tanhf(cn);
            cout[(size_t)row * HID + u] = cn;
            hout[(size_t)row * HID + u] = __float2half(hn);
        }
    }
}

// ---------------- fp16 mma.sync LSTM step (fp16 accumulation) ----------------
// grid (8 N-tiles, 2 cells, MSPLIT M-groups), 256 threads = 8 warps.
__global__ __launch_bounds__(256, 1) void cell_mma_kernel(
    int cell_base, const float* __restrict__ x0, const float* __restrict__ x1,
    int xstride, int rd, int use_comb, int use_fb)
{
    extern __shared__ char smem[];
    uint32_t* smA = (uint32_t*)(smem + SM_A);   // [2][128][AW]
    uint32_t* smB = (uint32_t*)(smem + SM_B);   // [8][128][AW]
    float* smWI = (float*)(smem + SM_WI);
    float* smBI = (float*)(smem + SM_BI);

    int tid = threadIdx.x;
    int wid = tid >> 5, lane = tid & 31;
    int gid = lane >> 2, tig = lane & 3;
    int cell = cell_base + blockIdx.y;
    const float* x = use_fb ? (blockIdx.y == 0 ? d_xs : d_xc)
                            : (blockIdx.y == 0 ? x0 : x1);
    const __half* hin = use_comb ? d_h0c : d_hbuf[cell][rd];
    const float*  cin = use_comb ? d_c0c : d_cbuf[cell];
    __half* hout = d_hbuf[cell][rd ^ 1];
    float*  cout = d_cbuf[cell];
    const float* Wh = d_W4h[cell];
    int nt = blockIdx.x;
    int col0 = nt << 7;
    int m_lo = (blockIdx.z * 128) / MSPLIT;
    int m_hi = ((blockIdx.z + 1) * 128) / MSPLIT;

    int r = tid >> 1, half = tid & 1;

    // ---- load resident weight tile (fp32 -> half2), Wi, bias ----
    {
        const float* wrow = Wh + (size_t)(col0 + r) * 256 + half * 16;
        #pragma unroll
        for (int c = 0; c < 8; c++) {
            const float* src = wrow + c * 32;
            uint32_t w[8];
            #pragma unroll
            for (int j = 0; j < 8; j++) {
                __half2 h2 = __floats2half2_rn(src[2 * j], src[2 * j + 1]);
                w[j] = *(uint32_t*)&h2;
            }
            uint32_t* dst = smB + ((size_t)c * 128 + r) * AW + half * 8;
            *(uint4*)(dst)     = make_uint4(w[0], w[1], w[2], w[3]);
            *(uint4*)(dst + 4) = make_uint4(w[4], w[5], w[6], w[7]);
        }
        if (tid < 128)
            *(float4*)(smWI + tid * 4) = *(const float4*)(d_W4i[cell] + (size_t)(col0 + tid) * 4);
        if (tid < 32)
            *(float4*)(smBI + tid * 4) = *(const float4*)(d_b4[cell] + col0 + tid * 4);
    }
    __syncthreads();

    // prologue: preload chunk 0 of first mtile
    uint4 va0, va1;
    {
        const uint4* arow = (const uint4*)(hin + (size_t)((m_lo << 7) + r) * 256 + half * 16);
        va0 = arow[0]; va1 = arow[1];
    }

    for (int mt = m_lo; mt < m_hi; mt++) {
        int row0 = mt << 7;
        const uint4* arow = (const uint4*)(hin + (size_t)(row0 + r) * 256 + half * 16);

        uint32_t acc[16][2];
        #pragma unroll
        for (int i = 0; i < 16; i++) { acc[i][0] = 0u; acc[i][1] = 0u; }

        for (int c = 0; c < 8; c++) {
            uint32_t* dst = smA + (size_t)((c & 1) * 128 + r) * AW + half * 8;
            *(uint4*)(dst)     = va0;
            *(uint4*)(dst + 4) = va1;
            __syncthreads();
            if (c < 7) {
                va0 = arow[(c + 1) * 4 + 0];
                va1 = arow[(c + 1) * 4 + 1];
            } else if (mt + 1 < m_hi) {
                const uint4* arow2 = (const uint4*)(hin + (size_t)(row0 + 128 + r) * 256 + half * 16);
                va0 = arow2[0]; va1 = arow2[1];
            }
            const uint32_t* Ab = smA + (size_t)((c & 1) * 128 + wid * 16) * AW;
            const uint32_t* Bb = smB + (size_t)c * 128 * AW;
            #pragma unroll
            for (int s = 0; s < 2; s++) {
                int kk = s * 8;
                uint32_t a0 = Ab[(size_t)gid * AW + kk + tig];
                uint32_t a1 = Ab[(size_t)(gid + 8) * AW + kk + tig];
                uint32_t a2 = Ab[(size_t)gid * AW + kk + tig + 4];
                uint32_t a3 = Ab[(size_t)(gid + 8) * AW + kk + tig + 4];
                #pragma unroll
                for (int n8 = 0; n8 < 16; n8++) {
                    uint32_t b0 = Bb[(size_t)(n8 * 8 + gid) * AW + kk + tig];
                    uint32_t b1 = Bb[(size_t)(n8 * 8 + gid) * AW + kk + tig + 4];
                    mma_f16acc(acc[n8], a0, a1, a2, a3, b0, b1);
                }
            }
        }

        // ---- fused LSTM epilogue (fast activations) ----
        #pragma unroll
        for (int rr = 0; rr < 2; rr++) {
            int row = row0 + wid * 16 + gid + rr * 8;
            float xv[4];
            #pragma unroll
            for (int s = 0; s < 4; s++) xv[s] = x[(size_t)row * xstride + s];
            #pragma unroll
            for (int j = 0; j < 4; j++) {
                int ub = 8 * j + 2 * tig;
                float2 cold = *(const float2*)(cin + (size_t)row * HID + nt * 32 + ub);
                float2 vi = __half22float2(*(__half2*)&acc[j     ][rr]);
                float2 vf = __half22float2(*(__half2*)&acc[j +  4][rr]);
                float2 vg = __half22float2(*(__half2*)&acc[j +  8][rr]);
                float2 vo = __half22float2(*(__half2*)&acc[j + 12][rr]);
                float hv[2], cv[2];
                #pragma unroll
                for (int e = 0; e < 2; e++) {
                    int u = ub + e;
                    float g_i = (e == 0 ? vi.x : vi.y) + smBI[u];
                    float g_f = (e == 0 ? vf.x : vf.y) + smBI[32 + u];
                    float g_g = (e == 0 ? vg.x : vg.y) + smBI[64 + u];
                    float g_o = (e == 0 ? vo.x : vo.y) + smBI[96 + u];
                    #pragma unroll
                    for (int s = 0; s < 4; s++) {
                        g_i = fmaf(smWI[u * 4 + s],        xv[s], g_i);
                        g_f = fmaf(smWI[(32 + u) * 4 + s], xv[s], g_f);
                        g_g = fmaf(smWI[(64 + u) * 4 + s], xv[s], g_g);
                        g_o = fmaf(smWI[(96 + u) * 4 + s], xv[s], g_o);
                    }
                    float co = (e == 0) ? cold.x : cold.y;
                    float cn = fmaf(sig_fast(gclamp(g_f)), co,
                                    sig_fast(gclamp(g_i)) * tanh_fast(gclamp(g_g)));
                    float hn = sig_fast(gclamp(g_o)) * tanh_fast(gclamp(cn));
                    cv[e] = cn; hv[e] = hn;
                }
                *(float2*)(cout + (size_t)row * HID + nt * 32 + ub) = make_float2(cv[0], cv[1]);
                *(__half2*)(hout + (size_t)row * HID + nt * 32 + ub) = __floats2half2_rn(hv[0], hv[1]);
            }
        }
    }
}

// ---------------- combine encoder finals ----------------
__global__ void combine_kernel() {
    size_t i = (size_t)blockIdx.x * blockDim.x + threadIdx.x;  // 0 .. NB*HID/4-1
    float4 c0 = ((const float4*)d_cbuf[0])[i];
    float4 c1 = ((const float4*)d_cbuf[1])[i];
    ((float4*)d_c0c)[i] = make_float4(c0.x + c1.x, c0.y + c1.y, c0.z + c1.z, c0.w + c1.w);
    const __half2* ha = (const __half2*)d_hbuf[0][0];
    const __half2* hb = (const __half2*)d_hbuf[1][0];
    __half2* ho = (__half2*)d_h0c;
    #pragma unroll
    for (int j = 0; j < 2; j++) {
        float2 a = __half22float2(ha[2 * i + j]);
        float2 b = __half22float2(hb[2 * i + j]);
        ho[2 * i + j] = __floats2half2_rn(a.x + b.x, a.y + b.y);
    }
}

// ---------------- decoder heads ----------------
__global__ void heads_kernel(int t, int parity,
    const float* __restrict__ fsw, const float* __restrict__ fsb,
    const float* __restrict__ fcw, const float* __restrict__ fcb,
    const float* __restrict__ ew,  const float* __restrict__ eb,
    float* __restrict__ out)
{
    int gtid = blockIdx.x * blockDim.x + threadIdx.x;
    int row  = gtid >> 5;
    int lane = gtid & 31;
    if (row >= NB) return;
    const __half* hs = d_hbuf[2][parity] + (size_t)row * HID;
    const __half* hc = d_hbuf[3][parity] + (size_t)row * HID;
    float vs[8], vc[8];
    #pragma unroll
    for (int i = 0; i < 8; i++) {
        vs[i] = __half2float(hs[lane + 32 * i]);
        vc[i] = __half2float(hc[lane + 32 * i]);
    }

    float r[10];
    #pragma unroll
    for (int o = 0; o < 4; o++) {
        float p = 0.f;
        #pragma unroll
        for (int i = 0; i < 8; i++) p = fmaf(fsw[o * 256 + lane + 32 * i], vs[i], p);
        r[o] = p;
    }
    #pragma unroll
    for (int o = 0; o < 2; o++) {
        float p = 0.f;
        #pragma unroll
        for (int i = 0; i < 8; i++) p = fmaf(fcw[o * 256 + lane + 32 * i], vc[i], p);
        r[4 + o] = p;
    }
    #pragma unroll
    for (int o = 0; o < 4; o++) {
        float p = 0.f;
        #pragma unroll
        for (int i = 0; i < 8; i++) p = fmaf(ew[o * 256 + lane + 32 * i], vc[i], p);
        r[6 + o] = p;
    }
    #pragma unroll
    for (int off = 16; off > 0; off >>= 1)
        #pragma unroll
        for (int o = 0; o < 10; o++) r[o] += __shfl_xor_sync(0xffffffffu, r[o], off);

    if (lane == 0) {
        #pragma unroll
        for (int s = 0; s < 4; s++) {
            float v = r[s] + fsb[s];
            v = fminf(fmaxf(v, -100.f), 100.f);
            out[(size_t)row * 64 + t * 4 + s] = v;
            d_xs[row * 4 + s] = v;
        }
        float l0 = fmaxf(r[4] + fcb[0], 0.f);
        float l1 = fmaxf(r[5] + fcb[1], 0.f);
        float m  = fmaxf(l0, l1);
        float e0 = expf(l0 - m), e1 = expf(l1 - m);
        float inv = 1.f / (e0 + e1);
        size_t cb = (size_t)NB * 64;
        out[cb + (size_t)row * 32 + t * 2 + 0] = e0 * inv;
        out[cb + (size_t)row * 32 + t * 2 + 1] = e1 * inv;
        #pragma unroll
        for (int s = 0; s < 4; s++) d_xc[row * 4 + s] = fmaxf(r[6 + s] + eb[s], 0.f);
    }
}

// ---------------- host ----------------
extern "C" void kernel_launch(void* const* d_in, const int* in_sizes, int n_in,
                              void* d_out, int out_size)
{
    (void)in_sizes; (void)n_in; (void)out_size;
    const float* speed = (const float*)d_in[0];
    const float* pos   = (const float*)d_in[1];

    cudaFuncSetAttribute(cell_mma_kernel, cudaFuncAttributeMaxDynamicSharedMemorySize, SM_TOTAL);

    for (int cell = 0; cell < 4; cell++) {
        int base = 2 + 4 * cell;
        prep_kernel<<<1024, 256>>>(cell,
            (const float*)d_in[base + 1],
            (const float*)d_in[base + 0],
            (const float*)d_in[base + 2],
            (const float*)d_in[base + 3]);
    }

    dim3 tgrid(8, 2, MSPLIT);

    // ---- encoders ----
    cell_first_kernel<<<dim3(8, 128, 2), 256>>>(speed, pos, 64);
    for (int t = 1; t < 16; t++)
        cell_mma_kernel<<<tgrid, 256, SM_TOTAL>>>(0, speed + 4 * t, pos + 4 * t, 64, t & 1, 0, 0);

    combine_kernel<<<4096, 256>>>();

    // ---- decoders ----
    const float* fsw = (const float*)d_in[18];
    const float* fsb = (const float*)d_in[19];
    const float* fcw = (const float*)d_in[20];
    const float* fcb = (const float*)d_in[21];
    const float* ew  = (const float*)d_in[22];
    const float* eb  = (const float*)d_in[23];
    float* out = (float*)d_out;

    for (int t = 0; t < TOUT; t++) {
        if (t == 0)
            cell_mma_kernel<<<tgrid, 256, SM_TOTAL>>>(2, speed + 60, pos + 60, 64, 0, 1, 0);
        else
            cell_mma_kernel<<<tgrid, 256, SM_TOTAL>>>(2, nullptr, nullptr, 4, t & 1, 0, 1);
        heads_kernel<<<2048, 256>>>(t, (t & 1) ^ 1, fsw, fsb, fcw, fcb, ew, eb, out);
    }
}

// round 7
// speedup vs baseline: 5.8120x; 1.0017x over previous
#include <cuda_runtime.h>
#include <cuda_fp16.h>
#include <math.h>
#include <stdint.h>

#define NB   16384
#define HID  256
#define TOUT 16
#define MSPLIT 9

// ---------------- persistent device scratch ----------------
__device__ float  d_W4h[4][1024 * 256];   // permuted recurrent weights [col'][k] (fp32)
__device__ float  d_W4i[4][1024 * 4];
__device__ float  d_b4 [4][1024];
__device__ __half d_hbuf[4][2][NB * HID]; // hidden state, fp16
__device__ float  d_cbuf[4][NB * HID];    // cell state, fp32
__device__ __half d_h0c[NB * HID];
__device__ float  d_c0c[NB * HID];
__device__ float  d_xs[NB * 4];
__device__ float  d_xc[NB * 4];

__device__ __forceinline__ float sigf(float x) { return 1.0f / (1.0f + expf(-x)); }

// fast activations (MUFU-based); callers clamp input to [-30, 30]
__device__ __forceinline__ float sig_fast(float x) {
    float e = __expf(-x);
    return __fdividef(1.0f, 1.0f + e);
}
__device__ __forceinline__ float tanh_fast(float x) {
    float e = __expf(-2.0f * x);
    return (1.0f - e) * __fdividef(1.0f, 1.0f + e);
}
__device__ __forceinline__ float gclamp(float x) {
    return fminf(fmaxf(x, -30.0f), 30.0f);
}

// fp16 mma with fp16 accumulators (d = 2x b32 regs, each half2)
__device__ __forceinline__ void mma_f16acc(uint32_t* d,
    uint32_t a0, uint32_t a1, uint32_t a2, uint32_t a3, uint32_t b0, uint32_t b1) {
    asm volatile("mma.sync.aligned.m16n8k16.row.col.f16.f16.f16.f16 "
        "{%0,%1}, {%2,%3,%4,%5}, {%6,%7}, {%0,%1};"
        : "+r"(d[0]), "+r"(d[1])
        : "r"(a0), "r"(a1), "r"(a2), "r"(a3), "r"(b0), "r"(b1));
}

// ---------------- SMEM layout ----------------
// word = uint32 holding half2 (2 halfs along k). Row stride 20 words (16 data + 4 pad)
#define AW 20
#define SM_WI   0                        // 128*4 floats = 2048 B
#define SM_BI   2048                     // 512 B
#define SM_A    2560                     // 2*128*20*4 = 20480 B
#define SM_B    23040                    // 8*128*20*4 = 81920 B
#define SM_TOTAL 104960

// ---------------- weight permutation ----------------
__global__ void prep_kernel(int cell,
                            const float* __restrict__ Whh,
                            const float* __restrict__ Wih,
                            const float* __restrict__ bih,
                            const float* __restrict__ bhh) {
    int colp = blockIdx.x;
    int k    = threadIdx.x;
    int g    = (colp & 127) >> 5;
    int u    = ((colp >> 7) << 5) + (colp & 31);
    int orig = g * 256 + u;
    d_W4h[cell][colp * 256 + k] = Whh[orig * 256 + k];
    if (k < 4) d_W4i[cell][colp * 4 + k] = Wih[orig * 4 + k];
    if (k == 0) d_b4[cell][colp] = bih[orig] + bhh[orig];
}

// ---------------- first step (h=c=0) ----------------
__global__ __launch_bounds__(256, 2) void cell_first_kernel(
    const float* __restrict__ x0, const float* __restrict__ x1, int xstride)
{
    int cell = blockIdx.z;
    const float* x = blockIdx.z == 0 ? x0 : x1;
    __half* hout = d_hbuf[cell][1];
    float*  cout = d_cbuf[cell];
    int row0 = blockIdx.y << 7;
    int col0 = blockIdx.x << 7;
    int tx = threadIdx.x & 15;
    int ty = threadIdx.x >> 4;

    float xv[8][4];
    #pragma unroll
    for (int rr = 0; rr < 8; rr++) {
        int row = row0 + (ty << 3) + rr;
        #pragma unroll
        for (int s = 0; s < 4; s++) xv[rr][s] = x[(size_t)row * xstride + s];
    }
    const float* Wi = d_W4i[cell];
    const float* bb = d_b4[cell];
    int ubase = blockIdx.x << 5;

    #pragma unroll
    for (int hh = 0; hh < 2; hh++) {
        int u = ubase + tx + (hh << 4);
        float wi[4][4], bg[4];
        #pragma unroll
        for (int g = 0; g < 4; g++) {
            int colp = col0 + (g << 5) + tx + (hh << 4);
            bg[g] = bb[colp];
            #pragma unroll
            for (int s = 0; s < 4; s++) wi[g][s] = Wi[colp * 4 + s];
        }
        #pragma unroll
        for (int rr = 0; rr < 8; rr++) {
            int row = row0 + (ty << 3) + rr;
            float gt[4];
            #pragma unroll
            for (int g = 0; g < 4; g++) {
                float v = bg[g];
                #pragma unroll
                for (int s = 0; s < 4; s++) v = fmaf(wi[g][s], xv[rr][s], v);
                gt[g] = v;
            }
            float ig = sigf(gt[0]);
            float gg = tanhf(gt[2]);
            float og = sigf(gt[3]);
            float cn = ig * gg;
            float hn = og * tanhf(cn);
            cout[(size_t)row * HID + u] = cn;
            hout[(size_t)row * HID + u] = __float2half(hn);
        }
    }
}

// ---------------- fp16 mma.sync LSTM step (fp16 accumulation) ----------------
// grid (8 N-tiles, 2 cells, MSPLIT M-groups), 256 threads = 8 warps.
__global__ __launch_bounds__(256, 1) void cell_mma_kernel(
    int cell_base, const float* __restrict__ x0, const float* __restrict__ x1,
    int xstride, int rd, int use_comb, int use_fb)
{
    extern __shared__ char smem[];
    uint32_t* smA = (uint32_t*)(smem + SM_A);   // [2][128][AW]
    uint32_t* smB = (uint32_t*)(smem + SM_B);   // [8][128][AW]
    float* smWI = (float*)(smem + SM_WI);
    float* smBI = (float*)(smem + SM_BI);

    int tid = threadIdx.x;
    int wid = tid >> 5, lane = tid & 31;
    int gid = lane >> 2, tig = lane & 3;
    int cell = cell_base + blockIdx.y;
    const float* x = use_fb ? (blockIdx.y == 0 ? d_xs : d_xc)
                            : (blockIdx.y == 0 ? x0 : x1);
    const __half* hin = use_comb ? d_h0c : d_hbuf[cell][rd];
    const float*  cin = use_comb ? d_c0c : d_cbuf[cell];
    __half* hout = d_hbuf[cell][rd ^ 1];
    float*  cout = d_cbuf[cell];
    const float* Wh = d_W4h[cell];
    int nt = blockIdx.x;
    int col0 = nt << 7;
    int m_lo = (blockIdx.z * 128) / MSPLIT;
    int m_hi = ((blockIdx.z + 1) * 128) / MSPLIT;

    int r = tid >> 1, half = tid & 1;

    // ---- load resident weight tile (fp32 -> half2), Wi, bias ----
    {
        const float* wrow = Wh + (size_t)(col0 + r) * 256 + half * 16;
        #pragma unroll
        for (int c = 0; c < 8; c++) {
            const float* src = wrow + c * 32;
            uint32_t w[8];
            #pragma unroll
            for (int j = 0; j < 8; j++) {
                __half2 h2 = __floats2half2_rn(src[2 * j], src[2 * j + 1]);
                w[j] = *(uint32_t*)&h2;
            }
            uint32_t* dst = smB + ((size_t)c * 128 + r) * AW + half * 8;
            *(uint4*)(dst)     = make_uint4(w[0], w[1], w[2], w[3]);
            *(uint4*)(dst + 4) = make_uint4(w[4], w[5], w[6], w[7]);
        }
        if (tid < 128)
            *(float4*)(smWI + tid * 4) = *(const float4*)(d_W4i[cell] + (size_t)(col0 + tid) * 4);
        if (tid < 32)
            *(float4*)(smBI + tid * 4) = *(const float4*)(d_b4[cell] + col0 + tid * 4);
    }
    __syncthreads();

    // prologue: preload chunk 0 of first mtile
    uint4 va0, va1;
    {
        const uint4* arow = (const uint4*)(hin + (size_t)((m_lo << 7) + r) * 256 + half * 16);
        va0 = arow[0]; va1 = arow[1];
    }

    for (int mt = m_lo; mt < m_hi; mt++) {
        int row0 = mt << 7;
        const uint4* arow = (const uint4*)(hin + (size_t)(row0 + r) * 256 + half * 16);

        uint32_t acc[16][2];
        #pragma unroll
        for (int i = 0; i < 16; i++) { acc[i][0] = 0u; acc[i][1] = 0u; }

        for (int c = 0; c < 8; c++) {
            uint32_t* dst = smA + (size_t)((c & 1) * 128 + r) * AW + half * 8;
            *(uint4*)(dst)     = va0;
            *(uint4*)(dst + 4) = va1;
            __syncthreads();
            if (c < 7) {
                va0 = arow[(c + 1) * 4 + 0];
                va1 = arow[(c + 1) * 4 + 1];
            } else if (mt + 1 < m_hi) {
                const uint4* arow2 = (const uint4*)(hin + (size_t)(row0 + 128 + r) * 256 + half * 16);
                va0 = arow2[0]; va1 = arow2[1];
            }
            const uint32_t* Ab = smA + (size_t)((c & 1) * 128 + wid * 16) * AW;
            const uint32_t* Bb = smB + (size_t)c * 128 * AW;
            #pragma unroll
            for (int s = 0; s < 2; s++) {
                int kk = s * 8;
                uint32_t a0 = Ab[(size_t)gid * AW + kk + tig];
                uint32_t a1 = Ab[(size_t)(gid + 8) * AW + kk + tig];
                uint32_t a2 = Ab[(size_t)gid * AW + kk + tig + 4];
                uint32_t a3 = Ab[(size_t)(gid + 8) * AW + kk + tig + 4];
                #pragma unroll
                for (int n8 = 0; n8 < 16; n8++) {
                    uint32_t b0 = Bb[(size_t)(n8 * 8 + gid) * AW + kk + tig];
                    uint32_t b1 = Bb[(size_t)(n8 * 8 + gid) * AW + kk + tig + 4];
                    mma_f16acc(acc[n8], a0, a1, a2, a3, b0, b1);
                }
            }
        }

        // ---- fused LSTM epilogue (fast activations) ----
        #pragma unroll
        for (int rr = 0; rr < 2; rr++) {
            int row = row0 + wid * 16 + gid + rr * 8;
            float xv[4];
            #pragma unroll
            for (int s = 0; s < 4; s++) xv[s] = x[(size_t)row * xstride + s];
            #pragma unroll
            for (int j = 0; j < 4; j++) {
                int ub = 8 * j + 2 * tig;
                float2 cold = *(const float2*)(cin + (size_t)row * HID + nt * 32 + ub);
                float2 vi = __half22float2(*(__half2*)&acc[j     ][rr]);
                float2 vf = __half22float2(*(__half2*)&acc[j +  4][rr]);
                float2 vg = __half22float2(*(__half2*)&acc[j +  8][rr]);
                float2 vo = __half22float2(*(__half2*)&acc[j + 12][rr]);
                float hv[2], cv[2];
                #pragma unroll
                for (int e = 0; e < 2; e++) {
                    int u = ub + e;
                    float g_i = (e == 0 ? vi.x : vi.y) + smBI[u];
                    float g_f = (e == 0 ? vf.x : vf.y) + smBI[32 + u];
                    float g_g = (e == 0 ? vg.x : vg.y) + smBI[64 + u];
                    float g_o = (e == 0 ? vo.x : vo.y) + smBI[96 + u];
                    #pragma unroll
                    for (int s = 0; s < 4; s++) {
                        g_i = fmaf(smWI[u * 4 + s],        xv[s], g_i);
                        g_f = fmaf(smWI[(32 + u) * 4 + s], xv[s], g_f);
                        g_g = fmaf(smWI[(64 + u) * 4 + s], xv[s], g_g);
                        g_o = fmaf(smWI[(96 + u) * 4 + s], xv[s], g_o);
                    }
                    float co = (e == 0) ? cold.x : cold.y;
                    float cn = fmaf(sig_fast(gclamp(g_f)), co,
                                    sig_fast(gclamp(g_i)) * tanh_fast(gclamp(g_g)));
                    float hn = sig_fast(gclamp(g_o)) * tanh_fast(gclamp(cn));
                    cv[e] = cn; hv[e] = hn;
                }
                *(float2*)(cout + (size_t)row * HID + nt * 32 + ub) = make_float2(cv[0], cv[1]);
                *(__half2*)(hout + (size_t)row * HID + nt * 32 + ub) = __floats2half2_rn(hv[0], hv[1]);
            }
        }
    }
}

// ---------------- combine encoder finals ----------------
__global__ void combine_kernel() {
    size_t i = (size_t)blockIdx.x * blockDim.x + threadIdx.x;  // 0 .. NB*HID/4-1
    float4 c0 = ((const float4*)d_cbuf[0])[i];
    float4 c1 = ((const float4*)d_cbuf[1])[i];
    ((float4*)d_c0c)[i] = make_float4(c0.x + c1.x, c0.y + c1.y, c0.z + c1.z, c0.w + c1.w);
    const __half2* ha = (const __half2*)d_hbuf[0][0];
    const __half2* hb = (const __half2*)d_hbuf[1][0];
    __half2* ho = (__half2*)d_h0c;
    #pragma unroll
    for (int j = 0; j < 2; j++) {
        float2 a = __half22float2(ha[2 * i + j]);
        float2 b = __half22float2(hb[2 * i + j]);
        ho[2 * i + j] = __floats2half2_rn(a.x + b.x, a.y + b.y);
    }
}

// ---------------- decoder heads ----------------
__global__ void heads_kernel(int t, int parity,
    const float* __restrict__ fsw, const float* __restrict__ fsb,
    const float* __restrict__ fcw, const float* __restrict__ fcb,
    const float* __restrict__ ew,  const float* __restrict__ eb,
    float* __restrict__ out)
{
    int gtid = blockIdx.x * blockDim.x + threadIdx.x;
    int row  = gtid >> 5;
    int lane = gtid & 31;
    if (row >= NB) return;
    const __half* hs = d_hbuf[2][parity] + (size_t)row * HID;
    const __half* hc = d_hbuf[3][parity] + (size_t)row * HID;
    float vs[8], vc[8];
    #pragma unroll
    for (int i = 0; i < 8; i++) {
        vs[i] = __half2float(hs[lane + 32 * i]);
        vc[i] = __half2float(hc[lane + 32 * i]);
    }

    float r[10];
    #pragma unroll
    for (int o = 0; o < 4; o++) {
        float p = 0.f;
        #pragma unroll
        for (int i = 0; i < 8; i++) p = fmaf(fsw[o * 256 + lane + 32 * i], vs[i], p);
        r[o] = p;
    }
    #pragma unroll
    for (int o = 0; o < 2; o++) {
        float p = 0.f;
        #pragma unroll
        for (int i = 0; i < 8; i++) p = fmaf(fcw[o * 256 + lane + 32 * i], vc[i], p);
        r[4 + o] = p;
    }
    #pragma unroll
    for (int o = 0; o < 4; o++) {
        float p = 0.f;
        #pragma unroll
        for (int i = 0; i < 8; i++) p = fmaf(ew[o * 256 + lane + 32 * i], vc[i], p);
        r[6 + o] = p;
    }
    #pragma unroll
    for (int off = 16; off > 0; off >>= 1)
        #pragma unroll
        for (int o = 0; o < 10; o++) r[o] += __shfl_xor_sync(0xffffffffu, r[o], off);

    if (lane == 0) {
        #pragma unroll
        for (int s = 0; s < 4; s++) {
            float v = r[s] + fsb[s];
            v = fminf(fmaxf(v, -100.f), 100.f);
            out[(size_t)row * 64 + t * 4 + s] = v;
            d_xs[row * 4 + s] = v;
        }
        float l0 = fmaxf(r[4] + fcb[0], 0.f);
        float l1 = fmaxf(r[5] + fcb[1], 0.f);
        float m  = fmaxf(l0, l1);
        float e0 = expf(l0 - m), e1 = expf(l1 - m);
        float inv = 1.f / (e0 + e1);
        size_t cb = (size_t)NB * 64;
        out[cb + (size_t)row * 32 + t * 2 + 0] = e0 * inv;
        out[cb + (size_t)row * 32 + t * 2 + 1] = e1 * inv;
        #pragma unroll
        for (int s = 0; s < 4; s++) d_xc[row * 4 + s] = fmaxf(r[6 + s] + eb[s], 0.f);
    }
}

// ---------------- host ----------------
extern "C" void kernel_launch(void* const* d_in, const int* in_sizes, int n_in,
                              void* d_out, int out_size)
{
    (void)in_sizes; (void)n_in; (void)out_size;
    const float* speed = (const float*)d_in[0];
    const float* pos   = (const float*)d_in[1];

    cudaFuncSetAttribute(cell_mma_kernel, cudaFuncAttributeMaxDynamicSharedMemorySize, SM_TOTAL);

    for (int cell = 0; cell < 4; cell++) {
        int base = 2 + 4 * cell;
        prep_kernel<<<1024, 256>>>(cell,
            (const float*)d_in[base + 1],
            (const float*)d_in[base + 0],
            (const float*)d_in[base + 2],
            (const float*)d_in[base + 3]);
    }

    dim3 tgrid(8, 2, MSPLIT);

    // ---- encoders ----
    cell_first_kernel<<<dim3(8, 128, 2), 256>>>(speed, pos, 64);
    for (int t = 1; t < 16; t++)
        cell_mma_kernel<<<tgrid, 256, SM_TOTAL>>>(0, speed + 4 * t, pos + 4 * t, 64, t & 1, 0, 0);

    combine_kernel<<<4096, 256>>>();

    // ---- decoders ----
    const float* fsw = (const float*)d_in[18];
    const float* fsb = (const float*)d_in[19];
    const float* fcw = (const float*)d_in[20];
    const float* fcb = (const float*)d_in[21];
    const float* ew  = (const float*)d_in[22];
    const float* eb  = (const float*)d_in[23];
    float* out = (float*)d_out;

    for (int t = 0; t < TOUT; t++) {
        if (t == 0)
            cell_mma_kernel<<<tgrid, 256, SM_TOTAL>>>(2, speed + 60, pos + 60, 64, 0, 1, 0);
        else
            cell_mma_kernel<<<tgrid, 256, SM_TOTAL>>>(2, nullptr, nullptr, 4, t & 1, 0, 1);
        heads_kernel<<<2048, 256>>>(t, (t & 1) ^ 1, fsw, fsb, fcw, fcb, ew, eb, out);
    }
}